// round 9
// baseline (speedup 1.0000x reference)
#include <cuda_runtime.h>
#include <math.h>

#define N_PTS   131072
#define WIDTH   256
#define P       16              // points per CTA, warp = point
#define THREADS 512
#define KT      32              // K tile rows
#define NT_LAYER 8              // 256/32 tiles per layer
#define N_TILES  40             // 5 hidden layers * 8
#define AS_PT   (WIDTH * 6)     // 1536 floats per point: [j][ch]
#define AS_FLOATS (P * AS_PT)   // 24576
#define BT_FLOATS (KT * WIDTH)  // 8192 floats per tile
#define B_FLOATS  (3 * BT_FLOATS)
#define SMEM_BYTES ((AS_FLOATS + B_FLOATS) * 4 + 128)   // 196736

typedef unsigned long long u64;

__device__ __forceinline__ float fast_tanh(float x) {
    float e = __expf(2.0f * x);
    return 1.0f - __fdividef(2.0f, e + 1.0f);
}
__device__ __forceinline__ u64 pack2(float a) {              // {a,a}
    u64 r; asm("mov.b64 %0, {%1, %1};" : "=l"(r) : "f"(a)); return r;
}
__device__ __forceinline__ u64 packpair(float a, float b) {  // {a,b}
    u64 r; asm("mov.b64 %0, {%1, %2};" : "=l"(r) : "f"(a), "f"(b)); return r;
}
__device__ __forceinline__ void ffma2(u64& acc, u64 a, u64 b) {
    asm("fma.rn.f32x2 %0, %1, %2, %0;" : "+l"(acc) : "l"(a), "l"(b));
}
__device__ __forceinline__ float2 unpack2(u64 v) {
    float2 f; asm("mov.b64 {%0, %1}, %2;" : "=f"(f.x), "=f"(f.y) : "l"(v)); return f;
}

// stage one 32x256 W tile into the 3-deep smem ring via cp.async (.cg: L2 only)
__device__ __forceinline__ void issue_tile(const float* const* shW,
                                           float* Bs, int gt, int t) {
    const float* src = shW[gt >> 3] + (gt & 7) * BT_FLOATS;
    float* dst = Bs + (gt % 3) * BT_FLOATS;
    #pragma unroll
    for (int c = 0; c < 4; c++) {
        int idx = (t + THREADS * c) * 4;             // float index, 16B chunks
        unsigned saddr = (unsigned)__cvta_generic_to_shared(dst + idx);
        asm volatile("cp.async.cg.shared.global [%0], [%1], 16;"
                     :: "r"(saddr), "l"(src + idx));
    }
    asm volatile("cp.async.commit_group;" ::: "memory");
}

__global__ void __launch_bounds__(THREADS, 1)
pde_kernel(const float* __restrict__ xyt,
           const float* __restrict__ w0, const float* __restrict__ b0,
           const float* __restrict__ w1, const float* __restrict__ b1,
           const float* __restrict__ w2, const float* __restrict__ b2,
           const float* __restrict__ w3, const float* __restrict__ b3,
           const float* __restrict__ w4, const float* __restrict__ b4,
           const float* __restrict__ w5, const float* __restrict__ b5,
           const float* __restrict__ w6, const float* __restrict__ b6,
           float* __restrict__ out)
{
    extern __shared__ float smem[];
    float* As = smem;                               // [P][256][6] warp-private
    float* Bs = smem + AS_FLOATS;                   // [3][KT][256]
    const float** shW = (const float**)(smem + AS_FLOATS + B_FLOATS); // 10 ptrs

    const int t  = threadIdx.x;
    const int p  = t >> 5;
    const int g  = t & 31;
    const int pg = blockIdx.x * P + p;

    if (t == 0) {
        shW[0] = w1; shW[1] = w2; shW[2] = w3; shW[3] = w4; shW[4] = w5;
        shW[5] = b1; shW[6] = b2; shW[7] = b3; shW[8] = b4; shW[9] = b5;
    }
    __syncthreads();

    // start the W pipeline: tiles 0,1 of layer 1 in flight during layer 0
    issue_tile(shW, Bs, 0, t);
    issue_tile(shW, Bs, 1, t);

    const float x  = xyt[3 * pg + 0];
    const float y  = xyt[3 * pg + 1];
    const float tm = xyt[3 * pg + 2];

    float* Ap = As + p * AS_PT;                     // this warp's block

    // ---------------- Layer 0: 3 -> 256 + tanh (warp-private) -------------
    #pragma unroll
    for (int m = 0; m < 4; m++) {
        #pragma unroll
        for (int e = 0; e < 2; e++) {
            int j = 2 * g + 64 * m + e;
            float wx = w0[j];
            float wy = w0[WIDTH + j];
            float wt = w0[2 * WIDTH + j];
            float z  = fmaf(x, wx, fmaf(y, wy, fmaf(tm, wt, b0[j])));
            float v  = fast_tanh(z);
            float s  = 1.0f - v * v;
            float* r = Ap + j * 6;
            r[0] = v;
            r[1] = s * wx;
            r[2] = s * wy;
            r[3] = s * wt;
            r[4] = -2.0f * v * s * wx * wx;
            r[5] = -2.0f * v * s * wy * wy;
        }
    }
    __syncwarp();

    // ---------------- Layers 1..5 -----------------------------------------
    for (int l = 0; l < 5; l++) {
        u64 acc2[6][4];
        #pragma unroll
        for (int c = 0; c < 6; c++)
            #pragma unroll
            for (int m = 0; m < 4; m++) acc2[c][m] = 0ull;

        for (int ti = 0; ti < NT_LAYER; ti++) {
            const int gt = l * NT_LAYER + ti;
            if (gt < N_TILES - 1)
                asm volatile("cp.async.wait_group 1;" ::: "memory");
            else
                asm volatile("cp.async.wait_group 0;" ::: "memory");
            __syncthreads();                         // tile gt visible; buf (gt+2)%3 free
            if (gt + 2 < N_TILES) issue_tile(shW, Bs, gt + 2, t);

            const float* Bbase = Bs + (gt % 3) * BT_FLOATS + 2 * g;
            const float* Ak    = Ap + (ti * KT) * 6;

            #pragma unroll 8
            for (int k = 0; k < KT; k++) {
                u64 ad[6];
                #pragma unroll
                for (int c = 0; c < 6; c++) ad[c] = pack2(Ak[c]); // scalar bcast
                Ak += 6;
                const float* br = Bbase + k * WIDTH;
                #pragma unroll
                for (int m = 0; m < 4; m++) {
                    u64 bv = *(const u64*)(br + 64 * m);  // {b_j,b_j+1}
                    #pragma unroll
                    for (int c = 0; c < 6; c++)
                        ffma2(acc2[c][m], ad[c], bv);
                }
            }
        }

        // epilogue: warp-private, no block sync
        const float* bias = shW[5 + l];
        #pragma unroll
        for (int m = 0; m < 4; m++) {
            float2 au   = unpack2(acc2[0][m]);
            float2 aux  = unpack2(acc2[1][m]);
            float2 auy  = unpack2(acc2[2][m]);
            float2 aut  = unpack2(acc2[3][m]);
            float2 auxx = unpack2(acc2[4][m]);
            float2 auyy = unpack2(acc2[5][m]);
            #pragma unroll
            for (int e = 0; e < 2; e++) {
                int j = 2 * g + 64 * m + e;
                float u   = (e ? au.y   : au.x) + bias[j];
                float ux  = (e ? aux.y  : aux.x);
                float uy  = (e ? auy.y  : auy.x);
                float ut  = (e ? aut.y  : aut.x);
                float uxx = (e ? auxx.y : auxx.x);
                float uyy = (e ? auyy.y : auyy.x);
                float v = fast_tanh(u);
                float s = 1.0f - v * v;
                float tvs = 2.0f * v * s;
                u64* r = (u64*)(Ap + j * 6);          // 8B aligned (24j bytes)
                r[0] = packpair(v,      s * ux);
                r[1] = packpair(s * uy, s * ut);
                r[2] = packpair(fmaf(s, uxx, -tvs * ux * ux),
                                fmaf(s, uyy, -tvs * uy * uy));
            }
        }
        __syncwarp();
    }

    // ---------------- Layer 6: 256 -> 1, pure warp reduction ---------------
    float h = 0.f, hx = 0.f, hy = 0.f, ht = 0.f, hxx = 0.f, hyy = 0.f;
    #pragma unroll
    for (int m = 0; m < 4; m++) {
        #pragma unroll
        for (int e = 0; e < 2; e++) {
            int j = 2 * g + 64 * m + e;
            float wv = w6[j];
            const float* r = Ap + j * 6;
            h   = fmaf(r[0], wv, h);
            hx  = fmaf(r[1], wv, hx);
            hy  = fmaf(r[2], wv, hy);
            ht  = fmaf(r[3], wv, ht);
            hxx = fmaf(r[4], wv, hxx);
            hyy = fmaf(r[5], wv, hyy);
        }
    }
    #pragma unroll
    for (int off = 16; off > 0; off >>= 1) {
        h   += __shfl_xor_sync(0xFFFFFFFFu, h,   off);
        hx  += __shfl_xor_sync(0xFFFFFFFFu, hx,  off);
        hy  += __shfl_xor_sync(0xFFFFFFFFu, hy,  off);
        ht  += __shfl_xor_sync(0xFFFFFFFFu, ht,  off);
        hxx += __shfl_xor_sync(0xFFFFFFFFu, hxx, off);
        hyy += __shfl_xor_sync(0xFFFFFFFFu, hyy, off);
    }

    if (g == 0) {
        h += b6[0];
        const float PI = 3.14159265358979323846f;
        float f = sinf(PI * x) * sinf(PI * y) * expf(-tm);
        out[pg] = ht - 0.5f * (h * (hxx + hyy) + hx * hx + hy * hy) - f;
    }
}

extern "C" void kernel_launch(void* const* d_in, const int* in_sizes, int n_in,
                              void* d_out, int out_size)
{
    const float* xyt = (const float*)d_in[0];
    const float* w0  = (const float*)d_in[1];
    const float* b0  = (const float*)d_in[2];
    const float* w1  = (const float*)d_in[3];
    const float* b1  = (const float*)d_in[4];
    const float* w2  = (const float*)d_in[5];
    const float* b2  = (const float*)d_in[6];
    const float* w3  = (const float*)d_in[7];
    const float* b3  = (const float*)d_in[8];
    const float* w4  = (const float*)d_in[9];
    const float* b4  = (const float*)d_in[10];
    const float* w5  = (const float*)d_in[11];
    const float* b5  = (const float*)d_in[12];
    const float* w6  = (const float*)d_in[13];
    const float* b6  = (const float*)d_in[14];

    cudaFuncSetAttribute(pde_kernel,
                         cudaFuncAttributeMaxDynamicSharedMemorySize,
                         SMEM_BYTES);

    dim3 grid(N_PTS / P);
    pde_kernel<<<grid, THREADS, SMEM_BYTES>>>(
        xyt, w0, b0, w1, b1, w2, b2, w3, b3, w4, b4, w5, b5, w6, b6,
        (float*)d_out);
}

// round 12
// speedup vs baseline: 1.8643x; 1.8643x over previous
#include <cuda_runtime.h>
#include <cuda_fp16.h>
#include <math.h>
#include <stdint.h>

#define N_PTS   131072
#define WIDTH   256
#define P       16
#define THREADS 512
#define NTILES  40               // 5 layers * 8 k-chunks of 32
#define TILE_B  32768u           // fp16 hi 16K + lo 16K

#define OFF_AHI 0
#define OFF_ALO 49152
#define OFF_B   98304
#define OFF_STG 163840           // 96*128 f32 = 49152
#define OFF_W6  212992
#define SMEM_BYTES (OFF_W6 + 1024)   // 214016

__device__ __align__(16) uint8_t g_B[NTILES * TILE_B];

// A/B 8x8-block layouts (bytes, fp16 elems)
__device__ __host__ __forceinline__ unsigned a_off(int r, int k) {
    return (unsigned)(((r >> 3) * 32 + (k >> 3)) * 128 + (r & 7) * 16 + (k & 7) * 2);
}
__device__ __host__ __forceinline__ unsigned b_off(int n, int kk) {
    return (unsigned)(((n >> 3) * 4 + (kk >> 3)) * 128 + (n & 7) * 16 + (kk & 7) * 2);
}
__device__ __forceinline__ unsigned sg_off(int r, int jl) {  // stage f32, xor-swizzled
    return (unsigned)(r * 512 + ((jl << 2) ^ ((r & 7) << 4)));
}
__device__ __forceinline__ float fast_tanh(float x) {
    float e = __expf(2.0f * x);
    return 1.0f - __fdividef(2.0f, e + 1.0f);
}
__device__ __forceinline__ void split_store(float v, char* hi, char* lo) {
    __half h = __float2half(v);
    *(__half*)hi = h;
    *(__half*)lo = __float2half(v - __half2float(h));
}
__device__ __forceinline__ void ldsm4(uint32_t* r, unsigned a) {
    asm volatile("ldmatrix.sync.aligned.m8n8.x4.shared.b16 {%0,%1,%2,%3}, [%4];"
                 : "=r"(r[0]), "=r"(r[1]), "=r"(r[2]), "=r"(r[3]) : "r"(a));
}
__device__ __forceinline__ void ldsm2(uint32_t* r, unsigned a) {
    asm volatile("ldmatrix.sync.aligned.m8n8.x2.shared.b16 {%0,%1}, [%2];"
                 : "=r"(r[0]), "=r"(r[1]) : "r"(a));
}
__device__ __forceinline__ void mma16816(float* c, const uint32_t* a, const uint32_t* b) {
    asm volatile("mma.sync.aligned.m16n8k16.row.col.f32.f16.f16.f32 "
                 "{%0,%1,%2,%3}, {%4,%5,%6,%7}, {%8,%9}, {%0,%1,%2,%3};"
                 : "+f"(c[0]), "+f"(c[1]), "+f"(c[2]), "+f"(c[3])
                 : "r"(a[0]), "r"(a[1]), "r"(a[2]), "r"(a[3]), "r"(b[0]), "r"(b[1]));
}
__device__ __forceinline__ void copy_tile(int T, unsigned sb, int t) {
    const char* src = (const char*)g_B + (size_t)T * TILE_B;
    unsigned dst = sb + OFF_B + (unsigned)(T & 1) * TILE_B;
    #pragma unroll
    for (int i = 0; i < 4; i++) {
        int o = (t + THREADS * i) * 16;
        asm volatile("cp.async.cg.shared.global [%0], [%1], 16;"
                     :: "r"(dst + o), "l"(src + o));
    }
    asm volatile("cp.async.commit_group;" ::: "memory");
}

// ---- prep: W[k][j] -> W^T hi/lo fp16, 8x8-blocked, 40 tiles --------------
__global__ void prep_kernel(const float* __restrict__ w1, const float* __restrict__ w2,
                            const float* __restrict__ w3, const float* __restrict__ w4,
                            const float* __restrict__ w5)
{
    int idx = blockIdx.x * blockDim.x + threadIdx.x;
    if (idx >= 5 * 65536) return;
    int l = idx >> 16, r = idx & 65535;
    int k = r >> 8, j = r & 255;
    const float* W = (l == 0) ? w1 : (l == 1) ? w2 : (l == 2) ? w3 : (l == 3) ? w4 : w5;
    float wv = W[k * 256 + j];
    __half hi = __float2half(wv);
    __half lo = __float2half(wv - __half2float(hi));
    uint8_t* tile = g_B + (size_t)(l * 8 + (k >> 5)) * TILE_B;
    unsigned o = b_off(j, k & 31);
    *(__half*)(tile + o) = hi;
    *(__half*)(tile + 16384 + o) = lo;
}

// ---- main ----------------------------------------------------------------
__global__ void __launch_bounds__(THREADS, 1)
pde_main(const float* __restrict__ xyt,
         const float* __restrict__ w0, const float* __restrict__ b0,
         const float* __restrict__ b1, const float* __restrict__ b2,
         const float* __restrict__ b3, const float* __restrict__ b4,
         const float* __restrict__ b5,
         const float* __restrict__ w6, const float* __restrict__ b6,
         float* __restrict__ out)
{
    extern __shared__ char smem[];
    unsigned sb = (unsigned)__cvta_generic_to_shared(smem);
    const int t = threadIdx.x, w = t >> 5, g = t & 31;
    const int wm = w >> 3, wn = w & 7;
    char* Ah = smem + OFF_AHI;
    char* Al = smem + OFF_ALO;
    float* stage = (float*)(smem + OFF_STG);
    float* w6s = (float*)(smem + OFF_W6);

    if (t < 256) w6s[t] = w6[t];
    copy_tile(0, sb, t);

    // ---- layer 0: warp = point ----
    const int pg = blockIdx.x * P + w;
    const float x = xyt[3 * pg], y = xyt[3 * pg + 1], tm = xyt[3 * pg + 2];
    #pragma unroll
    for (int q = 0; q < 8; q++) {
        int j = g + 32 * q;
        float wx = w0[j], wy = w0[WIDTH + j], wt = w0[2 * WIDTH + j];
        float z = fmaf(x, wx, fmaf(y, wy, fmaf(tm, wt, b0[j])));
        float v = fast_tanh(z);
        float s = 1.0f - v * v;
        float vals[6] = { v, s * wx, s * wy, s * wt,
                          -2.0f * v * s * wx * wx, -2.0f * v * s * wy * wy };
        #pragma unroll
        for (int c = 0; c < 6; c++) {
            unsigned o = a_off(c * 16 + w, j);
            split_store(vals[c], Ah + o, Al + o);
        }
    }

    // per-lane ldmatrix constants
    const int arow_in = (g & 7) + ((g >> 3) & 1) * 8;   // 0..15
    const int akhi = g >> 4;                             // +8 k for matrices 2,3
    unsigned rowoffA[3];
    #pragma unroll
    for (int mt = 0; mt < 3; mt++) {
        int r = 48 * wm + 16 * mt + arow_in;
        rowoffA[mt] = (unsigned)((r >> 3) * 4096 + (r & 7) * 16);
    }
    const int bnin = g & 7, bm = (g >> 3) & 1;           // lanes 0..15 meaningful
    const float* biasL[5] = { b1, b2, b3, b4, b5 };
    float acc6[6] = {0.f, 0.f, 0.f, 0.f, 0.f, 0.f};

    for (int l = 0; l < 5; l++) {
        float acc[3][4][4];
        #pragma unroll
        for (int mt = 0; mt < 3; mt++)
            #pragma unroll
            for (int nt = 0; nt < 4; nt++)
                #pragma unroll
                for (int i = 0; i < 4; i++) acc[mt][nt][i] = 0.f;

        for (int kc = 0; kc < 8; kc++) {
            const int T = 8 * l + kc;
            asm volatile("cp.async.wait_group 0;" ::: "memory");
            __syncthreads();
            if (T < NTILES - 1) copy_tile(T + 1, sb, t);

            unsigned bufHi = sb + OFF_B + (unsigned)(T & 1) * TILE_B;
            unsigned bufLo = bufHi + 16384u;

            #pragma unroll
            for (int ks = 0; ks < 2; ks++) {
                uint32_t bh[4][2], bl[4][2];
                unsigned bko = (unsigned)((2 * ks + bm) * 128 + bnin * 16);
                #pragma unroll
                for (int nt = 0; nt < 4; nt++) {
                    unsigned ro = (unsigned)((4 * wn + nt) * 512) + bko;
                    ldsm2(bh[nt], bufHi + ro);
                    ldsm2(bl[nt], bufLo + ro);
                }
                unsigned ako = (unsigned)((kc * 4 + ks * 2 + akhi) * 128);
                #pragma unroll
                for (int mt = 0; mt < 3; mt++) {
                    uint32_t ah[4], al[4];
                    ldsm4(ah, sb + OFF_AHI + rowoffA[mt] + ako);
                    ldsm4(al, sb + OFF_ALO + rowoffA[mt] + ako);
                    #pragma unroll
                    for (int nt = 0; nt < 4; nt++) {
                        mma16816(acc[mt][nt], ah, bh[nt]);
                        mma16816(acc[mt][nt], al, bh[nt]);
                        mma16816(acc[mt][nt], ah, bl[nt]);
                    }
                }
            }
        }

        // ---- epilogue: two 128-col phases through f32 stage ----
        const float* bias = biasL[l];
        const int gid = g >> 2, tig = g & 3;
        #pragma unroll
        for (int ph = 0; ph < 2; ph++) {
            if ((wn >> 2) == ph) {
                #pragma unroll
                for (int mt = 0; mt < 3; mt++) {
                    int r0 = 48 * wm + 16 * mt + gid;
                    #pragma unroll
                    for (int nt = 0; nt < 4; nt++) {
                        int jl = 32 * wn - 128 * ph + 8 * nt + 2 * tig;
                        *(float2*)((char*)stage + sg_off(r0, jl)) =
                            make_float2(acc[mt][nt][0], acc[mt][nt][1]);
                        *(float2*)((char*)stage + sg_off(r0 + 8, jl)) =
                            make_float2(acc[mt][nt][2], acc[mt][nt][3]);
                    }
                }
            }
            __syncthreads();
            // transform: warp = point
            #pragma unroll
            for (int i = 0; i < 4; i++) {
                int jl = g + 32 * i;
                int j = 128 * ph + jl;
                float d[6];
                #pragma unroll
                for (int c = 0; c < 6; c++)
                    d[c] = *(const float*)((const char*)stage + sg_off(c * 16 + w, jl));
                float u = d[0] + bias[j];
                float v = fast_tanh(u);
                float s = 1.0f - v * v;
                float tvs = 2.0f * v * s;
                float o0 = v;
                float o1 = s * d[1];
                float o2 = s * d[2];
                float o3 = s * d[3];
                float o4 = fmaf(s, d[4], -tvs * d[1] * d[1]);
                float o5 = fmaf(s, d[5], -tvs * d[2] * d[2]);
                if (l < 4) {
                    float os[6] = { o0, o1, o2, o3, o4, o5 };
                    #pragma unroll
                    for (int c = 0; c < 6; c++) {
                        unsigned o = a_off(c * 16 + w, j);
                        split_store(os[c], Ah + o, Al + o);
                    }
                } else {
                    float wv = w6s[j];
                    acc6[0] = fmaf(o0, wv, acc6[0]);
                    acc6[1] = fmaf(o1, wv, acc6[1]);
                    acc6[2] = fmaf(o2, wv, acc6[2]);
                    acc6[3] = fmaf(o3, wv, acc6[3]);
                    acc6[4] = fmaf(o4, wv, acc6[4]);
                    acc6[5] = fmaf(o5, wv, acc6[5]);
                }
            }
            __syncthreads();
        }
    }

    // ---- final: warp(=point) reduction + residual ----
    #pragma unroll
    for (int off = 16; off > 0; off >>= 1)
        #pragma unroll
        for (int c = 0; c < 6; c++)
            acc6[c] += __shfl_xor_sync(0xFFFFFFFFu, acc6[c], off);

    if (g == 0) {
        float h = acc6[0] + b6[0];
        const float PI = 3.14159265358979323846f;
        float f = sinf(PI * x) * sinf(PI * y) * expf(-tm);
        out[pg] = acc6[3] - 0.5f * (h * (acc6[4] + acc6[5])
                                    + acc6[1] * acc6[1] + acc6[2] * acc6[2]) - f;
    }
}

extern "C" void kernel_launch(void* const* d_in, const int* in_sizes, int n_in,
                              void* d_out, int out_size)
{
    const float* xyt = (const float*)d_in[0];
    const float* w0  = (const float*)d_in[1];
    const float* b0  = (const float*)d_in[2];
    const float* w1  = (const float*)d_in[3];
    const float* b1  = (const float*)d_in[4];
    const float* w2  = (const float*)d_in[5];
    const float* b2  = (const float*)d_in[6];
    const float* w3  = (const float*)d_in[7];
    const float* b3  = (const float*)d_in[8];
    const float* w4  = (const float*)d_in[9];
    const float* b4  = (const float*)d_in[10];
    const float* w5  = (const float*)d_in[11];
    const float* b5  = (const float*)d_in[12];
    const float* w6  = (const float*)d_in[13];
    const float* b6  = (const float*)d_in[14];

    prep_kernel<<<(5 * 65536 + 255) / 256, 256>>>(w1, w2, w3, w4, w5);

    cudaFuncSetAttribute(pde_main,
                         cudaFuncAttributeMaxDynamicSharedMemorySize, SMEM_BYTES);
    pde_main<<<N_PTS / P, THREADS, SMEM_BYTES>>>(
        xyt, w0, b0, b1, b2, b3, b4, b5, w6, b6, (float*)d_out);
}

// round 14
// speedup vs baseline: 2.0694x; 1.1100x over previous
#include <cuda_runtime.h>
#include <cuda_fp16.h>
#include <math.h>
#include <stdint.h>

#define N_PTS   131072
#define WIDTH   256
#define P       16
#define THREADS 512
#define NTILES  40               // 5 layers * 8 k-chunks of 32
#define TILE_B  32768u           // fp16 hi 16K + lo 16K

#define OFF_AHI 0
#define OFF_ALO 49152
#define OFF_B   98304
#define OFF_EX  163840           // 3 planes x (16 pts x 260 floats) = 3 x 16640
#define EX_PLANE 16640
#define OFF_W6  213760
#define OFF_RED 214784           // 16 pts x 6 ch x 8 wn floats = 3KB
#define SMEM_BYTES 217856

__device__ __align__(16) uint8_t g_B[NTILES * TILE_B];

// A/B 8x8-block layouts (bytes, fp16 elems)
__device__ __host__ __forceinline__ unsigned a_off(int r, int k) {
    return (unsigned)(((r >> 3) * 32 + (k >> 3)) * 128 + (r & 7) * 16 + (k & 7) * 2);
}
__device__ __host__ __forceinline__ unsigned b_off(int n, int kk) {
    return (unsigned)(((n >> 3) * 4 + (kk >> 3)) * 128 + (n & 7) * 16 + (kk & 7) * 2);
}
// exchange plane offset (bytes): plain padded rows, trivially correct
__device__ __forceinline__ unsigned ex_off(int pt, int j) {
    return (unsigned)((pt * 260 + j) * 4);
}
__device__ __forceinline__ float fast_tanh(float x) {
    float e = __expf(2.0f * x);
    return 1.0f - __fdividef(2.0f, e + 1.0f);
}
// split-store a column pair (j0, j0+1) of row r as hi/lo half2 (one STS32 each)
__device__ __forceinline__ void st_pair(char* Ah, char* Al, int r, int j0,
                                        float a, float b) {
    unsigned o = a_off(r, j0);
    __half ha = __float2half(a), hb = __float2half(b);
    *(__half2*)(Ah + o) = __halves2half2(ha, hb);
    *(__half2*)(Al + o) = __halves2half2(__float2half(a - __half2float(ha)),
                                         __float2half(b - __half2float(hb)));
}
__device__ __forceinline__ void ldsm4(uint32_t* r, unsigned a) {
    asm volatile("ldmatrix.sync.aligned.m8n8.x4.shared.b16 {%0,%1,%2,%3}, [%4];"
                 : "=r"(r[0]), "=r"(r[1]), "=r"(r[2]), "=r"(r[3]) : "r"(a));
}
__device__ __forceinline__ void ldsm2(uint32_t* r, unsigned a) {
    asm volatile("ldmatrix.sync.aligned.m8n8.x2.shared.b16 {%0,%1}, [%2];"
                 : "=r"(r[0]), "=r"(r[1]) : "r"(a));
}
__device__ __forceinline__ void mma16816(float* c, const uint32_t* a, const uint32_t* b) {
    asm volatile("mma.sync.aligned.m16n8k16.row.col.f32.f16.f16.f32 "
                 "{%0,%1,%2,%3}, {%4,%5,%6,%7}, {%8,%9}, {%0,%1,%2,%3};"
                 : "+f"(c[0]), "+f"(c[1]), "+f"(c[2]), "+f"(c[3])
                 : "r"(a[0]), "r"(a[1]), "r"(a[2]), "r"(a[3]), "r"(b[0]), "r"(b[1]));
}
__device__ __forceinline__ void copy_tile(int T, unsigned sb, int t) {
    const char* src = (const char*)g_B + (size_t)T * TILE_B;
    unsigned dst = sb + OFF_B + (unsigned)(T & 1) * TILE_B;
    #pragma unroll
    for (int i = 0; i < 4; i++) {
        int o = (t + THREADS * i) * 16;
        asm volatile("cp.async.cg.shared.global [%0], [%1], 16;"
                     :: "r"(dst + o), "l"(src + o));
    }
    asm volatile("cp.async.commit_group;" ::: "memory");
}

// ---- prep: W[k][j] -> W^T hi/lo fp16, 8x8-blocked, 40 tiles --------------
__global__ void prep_kernel(const float* __restrict__ w1, const float* __restrict__ w2,
                            const float* __restrict__ w3, const float* __restrict__ w4,
                            const float* __restrict__ w5)
{
    int idx = blockIdx.x * blockDim.x + threadIdx.x;
    if (idx >= 5 * 65536) return;
    int l = idx >> 16, r = idx & 65535;
    int k = r >> 8, j = r & 255;
    const float* W = (l == 0) ? w1 : (l == 1) ? w2 : (l == 2) ? w3 : (l == 3) ? w4 : w5;
    float wv = W[k * 256 + j];
    __half hi = __float2half(wv);
    __half lo = __float2half(wv - __half2float(hi));
    uint8_t* tile = g_B + (size_t)(l * 8 + (k >> 5)) * TILE_B;
    unsigned o = b_off(j, k & 31);
    *(__half*)(tile + o) = hi;
    *(__half*)(tile + 16384 + o) = lo;
}

// ---- main ----------------------------------------------------------------
__global__ void __launch_bounds__(THREADS, 1)
pde_main(const float* __restrict__ xyt,
         const float* __restrict__ w0, const float* __restrict__ b0,
         const float* __restrict__ b1, const float* __restrict__ b2,
         const float* __restrict__ b3, const float* __restrict__ b4,
         const float* __restrict__ b5,
         const float* __restrict__ w6, const float* __restrict__ b6,
         float* __restrict__ out)
{
    extern __shared__ char smem[];
    unsigned sb = (unsigned)__cvta_generic_to_shared(smem);
    const int t = threadIdx.x, w = t >> 5, g = t & 31;
    const int wm = w >> 3, wn = w & 7;
    char* Ah = smem + OFF_AHI;
    char* Al = smem + OFF_ALO;
    char* exS  = smem + OFF_EX;
    char* exQ1 = smem + OFF_EX + EX_PLANE;
    char* exQ2 = smem + OFF_EX + 2 * EX_PLANE;
    float* w6s = (float*)(smem + OFF_W6);
    float* red = (float*)(smem + OFF_RED);

    if (t < 256) w6s[t] = w6[t];
    copy_tile(0, sb, t);

    // ---- layer 0: warp = point ----
    {
        const int pg = blockIdx.x * P + w;
        const float x = xyt[3 * pg], y = xyt[3 * pg + 1], tm = xyt[3 * pg + 2];
        #pragma unroll
        for (int q = 0; q < 8; q++) {
            int j = g + 32 * q;
            float wx = w0[j], wy = w0[WIDTH + j], wt = w0[2 * WIDTH + j];
            float z = fmaf(x, wx, fmaf(y, wy, fmaf(tm, wt, b0[j])));
            float v = fast_tanh(z);
            float s = 1.0f - v * v;
            float vals[6] = { v, s * wx, s * wy, s * wt,
                              -2.0f * v * s * wx * wx, -2.0f * v * s * wy * wy };
            #pragma unroll
            for (int c = 0; c < 6; c++) {
                unsigned o = a_off(c * 16 + w, j);
                __half h = __float2half(vals[c]);
                *(__half*)(Ah + o) = h;
                *(__half*)(Al + o) = __float2half(vals[c] - __half2float(h));
            }
        }
    }

    // per-lane ldmatrix constants
    const int arow_in = (g & 7) + ((g >> 3) & 1) * 8;   // 0..15
    const int akhi = g >> 4;                             // +8 k for matrices 2,3
    unsigned rowoffA[3];
    #pragma unroll
    for (int mt = 0; mt < 3; mt++) {
        int r = 48 * wm + 16 * mt + arow_in;
        rowoffA[mt] = (unsigned)((r >> 3) * 4096 + (r & 7) * 16);
    }
    const int bnin = g & 7, bm = (g >> 3) & 1;
    const int gid = g >> 2, tig = g & 3;
    const float* biasL[5] = { b1, b2, b3, b4, b5 };

    for (int l = 0; l < 5; l++) {
        float acc[3][4][4];
        #pragma unroll
        for (int mt = 0; mt < 3; mt++)
            #pragma unroll
            for (int nt = 0; nt < 4; nt++)
                #pragma unroll
                for (int i = 0; i < 4; i++) acc[mt][nt][i] = 0.f;

        for (int kc = 0; kc < 8; kc++) {
            const int T = 8 * l + kc;
            asm volatile("cp.async.wait_group 0;" ::: "memory");
            __syncthreads();
            if (T < NTILES - 1) copy_tile(T + 1, sb, t);

            unsigned bufHi = sb + OFF_B + (unsigned)(T & 1) * TILE_B;
            unsigned bufLo = bufHi + 16384u;

            #pragma unroll
            for (int ks = 0; ks < 2; ks++) {
                uint32_t bh[4][2], bl[4][2];
                unsigned bko = (unsigned)((2 * ks + bm) * 128 + bnin * 16);
                #pragma unroll
                for (int nt = 0; nt < 4; nt++) {
                    unsigned ro = (unsigned)((4 * wn + nt) * 512) + bko;
                    ldsm2(bh[nt], bufHi + ro);
                    ldsm2(bl[nt], bufLo + ro);
                }
                unsigned ako = (unsigned)((kc * 4 + ks * 2 + akhi) * 128);
                #pragma unroll
                for (int mt = 0; mt < 3; mt++) {
                    uint32_t ah[4], al[4];
                    ldsm4(ah, sb + OFF_AHI + rowoffA[mt] + ako);
                    ldsm4(al, sb + OFF_ALO + rowoffA[mt] + ako);
                    #pragma unroll
                    for (int nt = 0; nt < 4; nt++) {
                        mma16816(acc[mt][nt], ah, bh[nt]);
                        mma16816(acc[mt][nt], al, bh[nt]);
                        mma16816(acc[mt][nt], ah, bl[nt]);
                    }
                }
            }
        }
        __syncthreads();     // ALL mainloop A/B reads complete before any A rewrite

        // ---- epilogue: fragment-direct two-group handoff ----
        float aP[2][3] = { {0.f, 0.f, 0.f}, {0.f, 0.f, 0.f} };

        if (wm == 0) {          // phase A: channels u, ux, uy
            const float* bias = biasL[l];
            #pragma unroll
            for (int nt = 0; nt < 4; nt++) {
                int j0 = 32 * wn + 8 * nt + 2 * tig;
                float2 bv = *(const float2*)(bias + j0);
                float2 wv = make_float2(0.f, 0.f);
                if (l == 4) wv = *(const float2*)(w6s + j0);
                #pragma unroll
                for (int hf = 0; hf < 2; hf++) {
                    int pt = gid + 8 * hf;
                    int ci = 2 * hf;
                    float u0 = acc[0][nt][ci] + bv.x;
                    float u1 = acc[0][nt][ci + 1] + bv.y;
                    float d1a = acc[1][nt][ci], d1b = acc[1][nt][ci + 1];
                    float d2a = acc[2][nt][ci], d2b = acc[2][nt][ci + 1];
                    float v0 = fast_tanh(u0), v1 = fast_tanh(u1);
                    float s0 = 1.f - v0 * v0, s1 = 1.f - v1 * v1;
                    float o1a = s0 * d1a, o1b = s1 * d1b;
                    float o2a = s0 * d2a, o2b = s1 * d2b;
                    unsigned eo = ex_off(pt, j0);
                    *(float2*)(exS + eo)  = make_float2(s0, s1);
                    *(float2*)(exQ1 + eo) = make_float2(2.f * v0 * o1a * d1a,
                                                        2.f * v1 * o1b * d1b);
                    *(float2*)(exQ2 + eo) = make_float2(2.f * v0 * o2a * d2a,
                                                        2.f * v1 * o2b * d2b);
                    if (l < 4) {
                        st_pair(Ah, Al, pt,      j0, v0,  v1);
                        st_pair(Ah, Al, 16 + pt, j0, o1a, o1b);
                        st_pair(Ah, Al, 32 + pt, j0, o2a, o2b);
                    } else {
                        aP[hf][0] = fmaf(v0,  wv.x, fmaf(v1,  wv.y, aP[hf][0]));
                        aP[hf][1] = fmaf(o1a, wv.x, fmaf(o1b, wv.y, aP[hf][1]));
                        aP[hf][2] = fmaf(o2a, wv.x, fmaf(o2b, wv.y, aP[hf][2]));
                    }
                }
            }
            if (l == 4) {
                #pragma unroll
                for (int hf = 0; hf < 2; hf++)
                    #pragma unroll
                    for (int c = 0; c < 3; c++) {
                        aP[hf][c] += __shfl_xor_sync(0xFFFFFFFFu, aP[hf][c], 1);
                        aP[hf][c] += __shfl_xor_sync(0xFFFFFFFFu, aP[hf][c], 2);
                    }
                if (tig == 0)
                    #pragma unroll
                    for (int hf = 0; hf < 2; hf++)
                        #pragma unroll
                        for (int c = 0; c < 3; c++)
                            red[((gid + 8 * hf) * 6 + c) * 8 + wn] = aP[hf][c];
            }
        }
        __syncthreads();
        if (wm == 1) {          // phase B: channels ut, uxx, uyy
            #pragma unroll
            for (int nt = 0; nt < 4; nt++) {
                int j0 = 32 * wn + 8 * nt + 2 * tig;
                float2 wv = make_float2(0.f, 0.f);
                if (l == 4) wv = *(const float2*)(w6s + j0);
                #pragma unroll
                for (int hf = 0; hf < 2; hf++) {
                    int pt = gid + 8 * hf;
                    int ci = 2 * hf;
                    unsigned eo = ex_off(pt, j0);
                    float2 sv = *(const float2*)(exS + eo);
                    float2 q1 = *(const float2*)(exQ1 + eo);
                    float2 q2 = *(const float2*)(exQ2 + eo);
                    float d3a = acc[0][nt][ci], d3b = acc[0][nt][ci + 1];
                    float d4a = acc[1][nt][ci], d4b = acc[1][nt][ci + 1];
                    float d5a = acc[2][nt][ci], d5b = acc[2][nt][ci + 1];
                    float o3a = sv.x * d3a, o3b = sv.y * d3b;
                    float o4a = fmaf(sv.x, d4a, -q1.x), o4b = fmaf(sv.y, d4b, -q1.y);
                    float o5a = fmaf(sv.x, d5a, -q2.x), o5b = fmaf(sv.y, d5b, -q2.y);
                    if (l < 4) {
                        st_pair(Ah, Al, 48 + pt, j0, o3a, o3b);
                        st_pair(Ah, Al, 64 + pt, j0, o4a, o4b);
                        st_pair(Ah, Al, 80 + pt, j0, o5a, o5b);
                    } else {
                        aP[hf][0] = fmaf(o3a, wv.x, fmaf(o3b, wv.y, aP[hf][0]));
                        aP[hf][1] = fmaf(o4a, wv.x, fmaf(o4b, wv.y, aP[hf][1]));
                        aP[hf][2] = fmaf(o5a, wv.x, fmaf(o5b, wv.y, aP[hf][2]));
                    }
                }
            }
            if (l == 4) {
                #pragma unroll
                for (int hf = 0; hf < 2; hf++)
                    #pragma unroll
                    for (int c = 0; c < 3; c++) {
                        aP[hf][c] += __shfl_xor_sync(0xFFFFFFFFu, aP[hf][c], 1);
                        aP[hf][c] += __shfl_xor_sync(0xFFFFFFFFu, aP[hf][c], 2);
                    }
                if (tig == 0)
                    #pragma unroll
                    for (int hf = 0; hf < 2; hf++)
                        #pragma unroll
                        for (int c = 0; c < 3; c++)
                            red[((gid + 8 * hf) * 6 + (3 + c)) * 8 + wn] = aP[hf][c];
            }
        }
    }

    // ---- final residual ----
    __syncthreads();
    if (t < P) {
        int pg = blockIdx.x * P + t;
        float s[6];
        #pragma unroll
        for (int c = 0; c < 6; c++) {
            float a = 0.f;
            #pragma unroll
            for (int wn2 = 0; wn2 < 8; wn2++) a += red[(t * 6 + c) * 8 + wn2];
            s[c] = a;
        }
        float xx = xyt[3 * pg], yy = xyt[3 * pg + 1], tt = xyt[3 * pg + 2];
        float h = s[0] + b6[0];
        const float PI = 3.14159265358979323846f;
        float f = sinf(PI * xx) * sinf(PI * yy) * expf(-tt);
        out[pg] = s[3] - 0.5f * (h * (s[4] + s[5]) + s[1] * s[1] + s[2] * s[2]) - f;
    }
}

extern "C" void kernel_launch(void* const* d_in, const int* in_sizes, int n_in,
                              void* d_out, int out_size)
{
    const float* xyt = (const float*)d_in[0];
    const float* w0  = (const float*)d_in[1];
    const float* b0  = (const float*)d_in[2];
    const float* w1  = (const float*)d_in[3];
    const float* b1  = (const float*)d_in[4];
    const float* w2  = (const float*)d_in[5];
    const float* b2  = (const float*)d_in[6];
    const float* w3  = (const float*)d_in[7];
    const float* b3  = (const float*)d_in[8];
    const float* w4  = (const float*)d_in[9];
    const float* b4  = (const float*)d_in[10];
    const float* w5  = (const float*)d_in[11];
    const float* b5  = (const float*)d_in[12];
    const float* w6  = (const float*)d_in[13];
    const float* b6  = (const float*)d_in[14];

    prep_kernel<<<(5 * 65536 + 255) / 256, 256>>>(w1, w2, w3, w4, w5);

    cudaFuncSetAttribute(pde_main,
                         cudaFuncAttributeMaxDynamicSharedMemorySize, SMEM_BYTES);
    pde_main<<<N_PTS / P, THREADS, SMEM_BYTES>>>(
        xyt, w0, b0, b1, b2, b3, b4, b5, w6, b6, (float*)d_out);
}

// round 16
// speedup vs baseline: 2.4378x; 1.1780x over previous
#include <cuda_runtime.h>
#include <cuda_fp16.h>
#include <math.h>
#include <stdint.h>

#define N_PTS   131072
#define WIDTH   256
#define P       8                // points per CTA; row = ch*8 + pt  (M=48)
#define THREADS 256
#define NTILES  80               // 5 layers * 16 k-chunks of 16
#define TILE_B  16384u           // fp16 hi 8K + lo 8K

#define OFF_AHI 0                // 48*256*2 = 24576
#define OFF_ALO 24576
#define OFF_B   49152            // 2 * 16384
#define OFF_W6  81920            // 1024
#define OFF_RED 82944            // 8 pts * 6 ch * 8 wn * 4B = 1536
#define SMEM_BYTES 84480

__device__ __align__(16) uint8_t g_B[NTILES * TILE_B];

// A layout: 48 rows x 256 cols, 8x8 blocks (row-group stride 4096B, k-block 128B)
__device__ __host__ __forceinline__ unsigned a_off(int r, int k) {
    return (unsigned)(((r >> 3) * 32 + (k >> 3)) * 128 + (r & 7) * 16 + (k & 7) * 2);
}
// B tile: 256 n x 16 k (n-group stride 256B, k-block 128B)
__device__ __host__ __forceinline__ unsigned b_off(int n, int kk) {
    return (unsigned)(((n >> 3) * 2 + (kk >> 3)) * 128 + (n & 7) * 16 + (kk & 7) * 2);
}
__device__ __forceinline__ float fast_tanh(float x) {
    float e = __expf(2.0f * x);
    return 1.0f - __fdividef(2.0f, e + 1.0f);
}
// split-store cols (j0, j0+1) of row r (one STS32 per plane)
__device__ __forceinline__ void st_pair(char* Ah, char* Al, int r, int j0,
                                        float a, float b) {
    unsigned o = a_off(r, j0);
    __half ha = __float2half(a), hb = __float2half(b);
    *(__half2*)(Ah + o) = __halves2half2(ha, hb);
    *(__half2*)(Al + o) = __halves2half2(__float2half(a - __half2float(ha)),
                                         __float2half(b - __half2float(hb)));
}
__device__ __forceinline__ void ldsm4(uint32_t* r, unsigned a) {
    asm volatile("ldmatrix.sync.aligned.m8n8.x4.shared.b16 {%0,%1,%2,%3}, [%4];"
                 : "=r"(r[0]), "=r"(r[1]), "=r"(r[2]), "=r"(r[3]) : "r"(a));
}
__device__ __forceinline__ void ldsm2(uint32_t* r, unsigned a) {
    asm volatile("ldmatrix.sync.aligned.m8n8.x2.shared.b16 {%0,%1}, [%2];"
                 : "=r"(r[0]), "=r"(r[1]) : "r"(a));
}
__device__ __forceinline__ void mma16816(float* c, const uint32_t* a, const uint32_t* b) {
    asm volatile("mma.sync.aligned.m16n8k16.row.col.f32.f16.f16.f32 "
                 "{%0,%1,%2,%3}, {%4,%5,%6,%7}, {%8,%9}, {%0,%1,%2,%3};"
                 : "+f"(c[0]), "+f"(c[1]), "+f"(c[2]), "+f"(c[3])
                 : "r"(a[0]), "r"(a[1]), "r"(a[2]), "r"(a[3]), "r"(b[0]), "r"(b[1]));
}
__device__ __forceinline__ void copy_tile(int T, unsigned sb, int t) {
    const char* src = (const char*)g_B + (size_t)T * TILE_B;
    unsigned dst = sb + OFF_B + (unsigned)(T & 1) * TILE_B;
    #pragma unroll
    for (int i = 0; i < 4; i++) {
        int o = (t + THREADS * i) * 16;
        asm volatile("cp.async.cg.shared.global [%0], [%1], 16;"
                     :: "r"(dst + o), "l"(src + o));
    }
    asm volatile("cp.async.commit_group;" ::: "memory");
}

// ---- prep: W[k][j] -> W^T hi/lo fp16, 80 tiles of 256n x 16k ---------------
__global__ void prep_kernel(const float* __restrict__ w1, const float* __restrict__ w2,
                            const float* __restrict__ w3, const float* __restrict__ w4,
                            const float* __restrict__ w5)
{
    int idx = blockIdx.x * blockDim.x + threadIdx.x;
    if (idx >= 5 * 65536) return;
    int l = idx >> 16, r = idx & 65535;
    int k = r >> 8, j = r & 255;
    const float* W = (l == 0) ? w1 : (l == 1) ? w2 : (l == 2) ? w3 : (l == 3) ? w4 : w5;
    float wv = W[k * 256 + j];
    __half hi = __float2half(wv);
    __half lo = __float2half(wv - __half2float(hi));
    uint8_t* tile = g_B + (size_t)(l * 16 + (k >> 4)) * TILE_B;
    unsigned o = b_off(j, k & 15);
    *(__half*)(tile + o) = hi;
    *(__half*)(tile + 8192 + o) = lo;
}

// ---- main ------------------------------------------------------------------
__global__ void __launch_bounds__(THREADS, 2)
pde_main(const float* __restrict__ xyt,
         const float* __restrict__ w0, const float* __restrict__ b0,
         const float* __restrict__ b1, const float* __restrict__ b2,
         const float* __restrict__ b3, const float* __restrict__ b4,
         const float* __restrict__ b5,
         const float* __restrict__ w6, const float* __restrict__ b6,
         float* __restrict__ out)
{
    extern __shared__ char smem[];
    unsigned sb = (unsigned)__cvta_generic_to_shared(smem);
    const int t = threadIdx.x, w = t >> 5, g = t & 31;
    const int wn = w;                        // all 8 warps span n
    char* Ah = smem + OFF_AHI;
    char* Al = smem + OFF_ALO;
    float* w6s = (float*)(smem + OFF_W6);
    float* red = (float*)(smem + OFF_RED);

    if (t < 256) w6s[t] = w6[t];
    copy_tile(0, sb, t);

    // ---- layer 0: warp = point (8 warps, 8 points) ----
    {
        const int pg = blockIdx.x * P + w;
        const float x = xyt[3 * pg], y = xyt[3 * pg + 1], tm = xyt[3 * pg + 2];
        #pragma unroll
        for (int q = 0; q < 8; q++) {
            int j = g + 32 * q;
            float wx = w0[j], wy = w0[WIDTH + j], wt = w0[2 * WIDTH + j];
            float z = fmaf(x, wx, fmaf(y, wy, fmaf(tm, wt, b0[j])));
            float v = fast_tanh(z);
            float s = 1.0f - v * v;
            float vals[6] = { v, s * wx, s * wy, s * wt,
                              -2.0f * v * s * wx * wx, -2.0f * v * s * wy * wy };
            #pragma unroll
            for (int c = 0; c < 6; c++) {
                unsigned o = a_off(c * 8 + w, j);
                __half h = __float2half(vals[c]);
                *(__half*)(Ah + o) = h;
                *(__half*)(Al + o) = __float2half(vals[c] - __half2float(h));
            }
        }
    }

    // per-lane ldmatrix constants
    const int arow_in = (g & 7) + ((g >> 3) & 1) * 8;   // 0..15
    const int akhi = g >> 4;                             // k+8 select for mats 2,3
    unsigned rowoffA[3];
    #pragma unroll
    for (int mt = 0; mt < 3; mt++) {
        int r = 16 * mt + arow_in;
        rowoffA[mt] = (unsigned)((r >> 3) * 4096 + (r & 7) * 16);
    }
    const int bnin = g & 7, bm = (g >> 3) & 1;
    const int gid = g >> 2, tig = g & 3;                 // pt = gid
    const float* biasL[5] = { b1, b2, b3, b4, b5 };
    float r6[6];

    for (int l = 0; l < 5; l++) {
        float acc[3][4][4];
        #pragma unroll
        for (int mt = 0; mt < 3; mt++)
            #pragma unroll
            for (int nt = 0; nt < 4; nt++)
                #pragma unroll
                for (int i = 0; i < 4; i++) acc[mt][nt][i] = 0.f;

        for (int kc = 0; kc < 16; kc++) {
            const int T = 16 * l + kc;
            asm volatile("cp.async.wait_group 0;" ::: "memory");
            __syncthreads();
            if (T < NTILES - 1) copy_tile(T + 1, sb, t);

            unsigned bufHi = sb + OFF_B + (unsigned)(T & 1) * TILE_B;
            unsigned bufLo = bufHi + 8192u;

            uint32_t bh[4][2], bl[4][2];
            unsigned bko = (unsigned)(bm * 128 + bnin * 16);
            #pragma unroll
            for (int nt = 0; nt < 4; nt++) {
                unsigned ro = (unsigned)((4 * wn + nt) * 256) + bko;
                ldsm2(bh[nt], bufHi + ro);
                ldsm2(bl[nt], bufLo + ro);
            }
            unsigned ako = (unsigned)((kc * 2 + akhi) * 128);
            #pragma unroll
            for (int mt = 0; mt < 3; mt++) {
                uint32_t ah[4], al[4];
                ldsm4(ah, sb + OFF_AHI + rowoffA[mt] + ako);
                ldsm4(al, sb + OFF_ALO + rowoffA[mt] + ako);
                #pragma unroll
                for (int nt = 0; nt < 4; nt++) {
                    mma16816(acc[mt][nt], ah, bh[nt]);
                    mma16816(acc[mt][nt], al, bh[nt]);
                    mma16816(acc[mt][nt], ah, bl[nt]);
                }
            }
        }
        __syncthreads();     // all mainloop A reads done before A rewrite

        // ---- epilogue: fully thread-local (row = ch*8 + pt) ----
        const float* bias = biasL[l];
        if (l == 4) {
            #pragma unroll
            for (int c = 0; c < 6; c++) r6[c] = 0.f;
        }
        #pragma unroll
        for (int nt = 0; nt < 4; nt++) {
            int j0 = 32 * wn + 8 * nt + 2 * tig;
            float2 bv = *(const float2*)(bias + j0);
            // ch = 2*mt + hf; fragment elems [2*hf], [2*hf+1] are cols j0, j0+1
            float u0  = acc[0][nt][0] + bv.x, u1  = acc[0][nt][1] + bv.y;
            float ux0 = acc[0][nt][2],        ux1 = acc[0][nt][3];
            float uy0 = acc[1][nt][0],        uy1 = acc[1][nt][1];
            float ut0 = acc[1][nt][2],        ut1 = acc[1][nt][3];
            float uxx0 = acc[2][nt][0],       uxx1 = acc[2][nt][1];
            float uyy0 = acc[2][nt][2],       uyy1 = acc[2][nt][3];
            float v0 = fast_tanh(u0), v1 = fast_tanh(u1);
            float s0 = 1.f - v0 * v0, s1 = 1.f - v1 * v1;
            float tvs0 = 2.f * v0 * s0, tvs1 = 2.f * v1 * s1;
            float o1a = s0 * ux0, o1b = s1 * ux1;
            float o2a = s0 * uy0, o2b = s1 * uy1;
            float o3a = s0 * ut0, o3b = s1 * ut1;
            float o4a = fmaf(s0, uxx0, -tvs0 * ux0 * ux0);
            float o4b = fmaf(s1, uxx1, -tvs1 * ux1 * ux1);
            float o5a = fmaf(s0, uyy0, -tvs0 * uy0 * uy0);
            float o5b = fmaf(s1, uyy1, -tvs1 * uy1 * uy1);
            if (l < 4) {
                st_pair(Ah, Al,      gid, j0, v0,  v1);
                st_pair(Ah, Al,  8 + gid, j0, o1a, o1b);
                st_pair(Ah, Al, 16 + gid, j0, o2a, o2b);
                st_pair(Ah, Al, 24 + gid, j0, o3a, o3b);
                st_pair(Ah, Al, 32 + gid, j0, o4a, o4b);
                st_pair(Ah, Al, 40 + gid, j0, o5a, o5b);
            } else {
                float2 wv = *(const float2*)(w6s + j0);
                r6[0] = fmaf(v0,  wv.x, fmaf(v1,  wv.y, r6[0]));
                r6[1] = fmaf(o1a, wv.x, fmaf(o1b, wv.y, r6[1]));
                r6[2] = fmaf(o2a, wv.x, fmaf(o2b, wv.y, r6[2]));
                r6[3] = fmaf(o3a, wv.x, fmaf(o3b, wv.y, r6[3]));
                r6[4] = fmaf(o4a, wv.x, fmaf(o4b, wv.y, r6[4]));
                r6[5] = fmaf(o5a, wv.x, fmaf(o5b, wv.y, r6[5]));
            }
        }
    }

    // ---- w6 partials: reduce over tig, stash per (pt, ch, wn) ----
    #pragma unroll
    for (int c = 0; c < 6; c++) {
        r6[c] += __shfl_xor_sync(0xFFFFFFFFu, r6[c], 1);
        r6[c] += __shfl_xor_sync(0xFFFFFFFFu, r6[c], 2);
    }
    if (tig == 0)
        #pragma unroll
        for (int c = 0; c < 6; c++)
            red[(gid * 6 + c) * 8 + wn] = r6[c];
    __syncthreads();

    if (t < P) {
        int pg = blockIdx.x * P + t;
        float s[6];
        #pragma unroll
        for (int c = 0; c < 6; c++) {
            float a = 0.f;
            #pragma unroll
            for (int q = 0; q < 8; q++) a += red[(t * 6 + c) * 8 + q];
            s[c] = a;
        }
        float xx = xyt[3 * pg], yy = xyt[3 * pg + 1], tt = xyt[3 * pg + 2];
        float h = s[0] + b6[0];
        const float PI = 3.14159265358979323846f;
        float f = sinf(PI * xx) * sinf(PI * yy) * expf(-tt);
        out[pg] = s[3] - 0.5f * (h * (s[4] + s[5]) + s[1] * s[1] + s[2] * s[2]) - f;
    }
}

extern "C" void kernel_launch(void* const* d_in, const int* in_sizes, int n_in,
                              void* d_out, int out_size)
{
    const float* xyt = (const float*)d_in[0];
    const float* w0  = (const float*)d_in[1];
    const float* b0  = (const float*)d_in[2];
    const float* w1  = (const float*)d_in[3];
    const float* b1  = (const float*)d_in[4];
    const float* w2  = (const float*)d_in[5];
    const float* b2  = (const float*)d_in[6];
    const float* w3  = (const float*)d_in[7];
    const float* b3  = (const float*)d_in[8];
    const float* w4  = (const float*)d_in[9];
    const float* b4  = (const float*)d_in[10];
    const float* w5  = (const float*)d_in[11];
    const float* b5  = (const float*)d_in[12];
    const float* w6  = (const float*)d_in[13];
    const float* b6  = (const float*)d_in[14];

    prep_kernel<<<(5 * 65536 + 255) / 256, 256>>>(w1, w2, w3, w4, w5);

    cudaFuncSetAttribute(pde_main,
                         cudaFuncAttributeMaxDynamicSharedMemorySize, SMEM_BYTES);
    pde_main<<<N_PTS / P, THREADS, SMEM_BYTES>>>(
        xyt, w0, b0, b1, b2, b3, b4, b5, w6, b6, (float*)d_out);
}